// round 1
// baseline (speedup 1.0000x reference)
#include <cuda_runtime.h>
#include <cstdint>

// ---------------------------------------------------------------------------
// TT-linear, exploiting the rank-64 bottleneck:
//   W = A(4096x64) @ B(64x4096);  y = (x @ B^T) @ A^T + b
// Scratch (no allocations allowed -> __device__ globals)
// ---------------------------------------------------------------------------
__device__ __align__(256) float g_w01[16 * 1024];      // fold(core0,core1): (16,1024)
__device__ __align__(256) float g_A[256 * 1024];       // A flat: (4096,64) == (256,1024)
__device__ __align__(256) float g_B1[1024 * 1024];     // fold(core3,core4): (1024,1024)
__device__ __align__(256) float g_B[64 * 4096];        // B: (64,4096)
__device__ __align__(256) float g_T[2][8192 * 64];     // split-K partials of t = x @ B^T

// Packed f32x2 FMA (Blackwell; ptxas won't auto-fuse, must come from PTX)
__device__ __forceinline__ float2 ffma2(float2 a, float2 b, float2 c) {
    unsigned long long ra = *reinterpret_cast<unsigned long long*>(&a);
    unsigned long long rb = *reinterpret_cast<unsigned long long*>(&b);
    unsigned long long rc = *reinterpret_cast<unsigned long long*>(&c);
    unsigned long long rd;
    asm("fma.rn.f32x2 %0, %1, %2, %3;" : "=l"(rd) : "l"(ra), "l"(rb), "l"(rc));
    return *reinterpret_cast<float2*>(&rd);
}

// ---------------------------------------------------------------------------
// Fold kernels (tiny): build A and B from the 6 TT cores.
// core shapes: G0(1,16,64) G1(64,16,64) G2(64,16,64) G3(64,16,64) G4(64,16,64) G5(64,16,1)
// ---------------------------------------------------------------------------
__global__ void fold1_kernel(const float* __restrict__ G0, const float* __restrict__ G1) {
    // w01[s0][(s1,r2)] = sum_r1 G0[s0,r1] * G1[r1,(s1,r2)]   (16 x 1024)
    int i = blockIdx.x * 256 + threadIdx.x;   // 16384
    int row = i >> 10, col = i & 1023;
    float s = 0.f;
#pragma unroll 16
    for (int r1 = 0; r1 < 64; ++r1) s += G0[row * 64 + r1] * G1[r1 * 1024 + col];
    g_w01[i] = s;
}

__global__ void fold2_kernel(const float* __restrict__ G2) {
    // A[(s0,s1),(s2,r3)] = sum_r2 w01[(s0,s1),r2] * G2[r2,(s2,r3)]   (256 x 1024)
    // flat (256,1024) row-major == flat (4096,64) row-major -> store at i directly
    int i = blockIdx.x * 256 + threadIdx.x;   // 262144
    int row = i >> 10, col = i & 1023;
    float s = 0.f;
#pragma unroll 16
    for (int r2 = 0; r2 < 64; ++r2) s += g_w01[row * 64 + r2] * G2[r2 * 1024 + col];
    g_A[i] = s;
}

__global__ void foldB1_kernel(const float* __restrict__ G3, const float* __restrict__ G4) {
    // B1[(r3,s3),(s4,r5)] = sum_r4 G3[(r3,s3),r4] * G4[r4,(s4,r5)]   (1024 x 1024)
    int i = blockIdx.x * 256 + threadIdx.x;   // 1048576
    int row = i >> 10, col = i & 1023;
    float s = 0.f;
#pragma unroll 16
    for (int r4 = 0; r4 < 64; ++r4) s += G3[row * 64 + r4] * G4[r4 * 1024 + col];
    g_B1[i] = s;
}

__global__ void foldB2_kernel(const float* __restrict__ G5) {
    // B[r3,(s3,s4,s5)] = sum_r5 B1[(r3,s3,s4),r5] * G5[r5,s5]
    // flat index of output == i (checked: r3*4096 + (s3*16+s4)*16 + s5 == row*16+s5)
    int i = blockIdx.x * 256 + threadIdx.x;   // 262144
    int row = i >> 4, s5 = i & 15;
    float s = 0.f;
#pragma unroll
    for (int r5 = 0; r5 < 64; ++r5) s += g_B1[row * 64 + r5] * G5[r5 * 16 + s5];
    g_B[i] = s;
}

// ---------------------------------------------------------------------------
// GEMM1: t[n,r] = sum_k x[n,k] * B[r,k]     M=8192, N=64, K=4096
// Split-K=2 (grid 128x2 -> 256 blocks for occupancy). Block: 64 tok x 64 r,
// 128 threads, thread tile 8 tok x 4 r (as 2 f32x2 pairs). All inner-loop
// smem reads are bank-conflict-free (r strided by 16 across the jj dim).
// ---------------------------------------------------------------------------
__global__ __launch_bounds__(128) void gemm1_kernel(const float* __restrict__ x) {
    __shared__ float sx[64][33];   // [tok][k]
    __shared__ float sb[64][33];   // [r][k]
    const int tid = threadIdx.x;
    const int tx = tid & 15;       // r = tx + 16*jj, jj in 0..3
    const int ty = tid >> 4;       // tokens ty*8 .. ty*8+7
    const int tok0 = blockIdx.x * 64;
    const int ky = blockIdx.y;     // K half
    const int kbase = ky * 2048;

    float2 acc[8][2];
#pragma unroll
    for (int i = 0; i < 8; ++i) { acc[i][0] = make_float2(0.f, 0.f); acc[i][1] = make_float2(0.f, 0.f); }

    for (int k0 = kbase; k0 < kbase + 2048; k0 += 32) {
        // fill tiles: 64x32 each, 128 threads x 4 float4
#pragma unroll
        for (int l = 0; l < 4; ++l) {
            int s = tid + 128 * l;        // 0..511 float4 slots
            int row = s >> 3;             // 0..63
            int kq = (s & 7) * 4;         // 0..28
            float4 v = *reinterpret_cast<const float4*>(&x[(size_t)(tok0 + row) * 4096 + k0 + kq]);
            sx[row][kq + 0] = v.x; sx[row][kq + 1] = v.y; sx[row][kq + 2] = v.z; sx[row][kq + 3] = v.w;
            float4 w = *reinterpret_cast<const float4*>(&g_B[(size_t)row * 4096 + k0 + kq]);
            sb[row][kq + 0] = w.x; sb[row][kq + 1] = w.y; sb[row][kq + 2] = w.z; sb[row][kq + 3] = w.w;
        }
        __syncthreads();

#pragma unroll
        for (int kk = 0; kk < 32; ++kk) {
            float a[8];
#pragma unroll
            for (int i = 0; i < 8; ++i) a[i] = sx[ty * 8 + i][kk];
            float2 bp0 = make_float2(sb[tx][kk],      sb[tx + 16][kk]);
            float2 bp1 = make_float2(sb[tx + 32][kk], sb[tx + 48][kk]);
#pragma unroll
            for (int i = 0; i < 8; ++i) {
                float2 av = make_float2(a[i], a[i]);
                acc[i][0] = ffma2(av, bp0, acc[i][0]);
                acc[i][1] = ffma2(av, bp1, acc[i][1]);
            }
        }
        __syncthreads();
    }

#pragma unroll
    for (int i = 0; i < 8; ++i) {
        int n = tok0 + ty * 8 + i;
        float* tr = &g_T[ky][(size_t)n * 64];
        tr[tx]      = acc[i][0].x;
        tr[tx + 16] = acc[i][0].y;
        tr[tx + 32] = acc[i][1].x;
        tr[tx + 48] = acc[i][1].y;
    }
}

// ---------------------------------------------------------------------------
// GEMM2: y[n,o] = sum_r t[n,r] * A[o,r] + b[o]   M=8192, N=4096, K=64
// Block: 64 tok x 128 out, 128 threads, thread tile 8 tok x 8 out.
// K=64 entirely in smem; t split-K partials reduced during tile load.
// out assigned strided (out = tx + 16*jj) -> conflict-free scalar b-reads.
// ---------------------------------------------------------------------------
__global__ __launch_bounds__(128) void gemm2_kernel(const float* __restrict__ bias,
                                                    float* __restrict__ y) {
    extern __shared__ float smem[];
    float (*st)[65] = reinterpret_cast<float (*)[65]>(smem);             // [64 tok][65]
    float (*sa)[65] = reinterpret_cast<float (*)[65]>(smem + 64 * 65);   // [128 out][65]
    const int tid = threadIdx.x;
    const int tx = tid & 15;     // out = tx + 16*jj, jj in 0..7
    const int ty = tid >> 4;     // tokens ty*8 .. ty*8+7
    const int tok0 = blockIdx.x * 64;
    const int out0 = blockIdx.y * 128;

    // t tile 64x64 (reduce the two split-K partials while loading)
#pragma unroll
    for (int l = 0; l < 8; ++l) {
        int s = tid + 128 * l;     // 0..1023 float4 slots
        int row = s >> 4;          // 0..63
        int c = (s & 15) * 4;
        float4 v0 = *reinterpret_cast<const float4*>(&g_T[0][(size_t)(tok0 + row) * 64 + c]);
        float4 v1 = *reinterpret_cast<const float4*>(&g_T[1][(size_t)(tok0 + row) * 64 + c]);
        st[row][c + 0] = v0.x + v1.x; st[row][c + 1] = v0.y + v1.y;
        st[row][c + 2] = v0.z + v1.z; st[row][c + 3] = v0.w + v1.w;
    }
    // A tile 128x64
#pragma unroll
    for (int l = 0; l < 16; ++l) {
        int s = tid + 128 * l;     // 0..2047 float4 slots
        int row = s >> 4;          // 0..127
        int c = (s & 15) * 4;
        float4 v = *reinterpret_cast<const float4*>(&g_A[(size_t)(out0 + row) * 64 + c]);
        sa[row][c + 0] = v.x; sa[row][c + 1] = v.y; sa[row][c + 2] = v.z; sa[row][c + 3] = v.w;
    }
    __syncthreads();

    float2 acc[8][4];
#pragma unroll
    for (int i = 0; i < 8; ++i)
#pragma unroll
        for (int p = 0; p < 4; ++p) acc[i][p] = make_float2(0.f, 0.f);

#pragma unroll
    for (int r = 0; r < 64; ++r) {
        float a[8];
#pragma unroll
        for (int i = 0; i < 8; ++i) a[i] = st[ty * 8 + i][r];
        float2 bp[4];
#pragma unroll
        for (int p = 0; p < 4; ++p)
            bp[p] = make_float2(sa[tx + 16 * (2 * p)][r], sa[tx + 16 * (2 * p + 1)][r]);
#pragma unroll
        for (int i = 0; i < 8; ++i) {
            float2 av = make_float2(a[i], a[i]);
#pragma unroll
            for (int p = 0; p < 4; ++p) acc[i][p] = ffma2(av, bp[p], acc[i][p]);
        }
    }

    float bv[8];
#pragma unroll
    for (int jj = 0; jj < 8; ++jj) bv[jj] = bias[out0 + tx + 16 * jj];

#pragma unroll
    for (int i = 0; i < 8; ++i) {
        int n = tok0 + ty * 8 + i;
        float* yr = y + (size_t)n * 4096 + out0;
#pragma unroll
        for (int p = 0; p < 4; ++p) {
            yr[tx + 16 * (2 * p)]     = acc[i][p].x + bv[2 * p];
            yr[tx + 16 * (2 * p + 1)] = acc[i][p].y + bv[2 * p + 1];
        }
    }
}

// ---------------------------------------------------------------------------
// Launch
// ---------------------------------------------------------------------------
extern "C" void kernel_launch(void* const* d_in, const int* in_sizes, int n_in,
                              void* d_out, int out_size) {
    // Robust input identification by element count (core0/core5 by order):
    //   core0: 1024, core1..4: 65536, core5: 1024, x: 33554432, b: 4096
    const float* core[6] = {nullptr, nullptr, nullptr, nullptr, nullptr, nullptr};
    const float* x = nullptr;
    const float* bias = nullptr;
    int c64 = 1;
    for (int i = 0; i < n_in; ++i) {
        int sz = in_sizes[i];
        const float* p = reinterpret_cast<const float*>(d_in[i]);
        if (sz == 8192 * 4096) x = p;
        else if (sz == 4096) bias = p;
        else if (sz == 65536) { if (c64 <= 4) core[c64++] = p; }
        else if (sz == 1024) { if (!core[0]) core[0] = p; else core[5] = p; }
    }
    float* y = reinterpret_cast<float*>(d_out);

    const int g2_smem = (64 * 65 + 128 * 65) * (int)sizeof(float);  // 49920 B
    cudaFuncSetAttribute(gemm2_kernel, cudaFuncAttributeMaxDynamicSharedMemorySize, g2_smem);

    fold1_kernel<<<64, 256>>>(core[0], core[1]);
    fold2_kernel<<<1024, 256>>>(core[2]);
    foldB1_kernel<<<4096, 256>>>(core[3], core[4]);
    foldB2_kernel<<<1024, 256>>>(core[5]);
    gemm1_kernel<<<dim3(128, 2), 128>>>(x);
    gemm2_kernel<<<dim3(128, 32), 128, g2_smem>>>(bias, y);
}